// round 17
// baseline (speedup 1.0000x reference)
#include <cuda_runtime.h>
#include <cstdint>
#include <cstddef>

namespace cfg {
constexpr int T = 128;
constexpr int E = 256;
constexpr int H = 64;

// Per-CTA smem (112 KB total -> 2 CTAs/SM).
constexpr int A_B    = 0;        // 32 KB: x-hi fp16 image of ONE k-chunk (reconverted)
constexpr int BBUF_B = 32768;    // 32 KB: 2 x 16 KB W-piece double buffer
constexpr int QHI_B  = 65536;    // 16 KB (Q scaled 1/8, hi only)
constexpr int KHI_B  = 81920;    // 16 KB
constexpr int VHI_B  = 98304;    // 16 KB -> ends 114688
constexpr int SMEM_BYTES = 114688;
}

// W^T fp16 (hi only) swizzled images: [chunk(2)][row n(192)][256B]
__device__ __align__(16) unsigned char g_Wh[2 * 49152];

// ---------------------------------------------------------------------------
static __device__ __forceinline__ uint32_t smem_u32(const void* p) {
    uint32_t a;
    asm("{ .reg .u64 t; cvta.to.shared.u64 t, %1; cvt.u32.u64 %0, t; }" : "=r"(a) : "l"(p));
    return a;
}
static __device__ __forceinline__ uint32_t pkh(float f0, float f1) {
    uint32_t r;  // lower half = f16(f0), upper = f16(f1)
    asm("cvt.rn.f16x2.f32 %0, %1, %2;" : "=r"(r) : "f"(f1), "f"(f0));
    return r;
}
static __device__ __forceinline__ void ldsm4(uint32_t r[4], uint32_t addr) {
    asm volatile("ldmatrix.sync.aligned.m8n8.x4.shared.b16 {%0,%1,%2,%3}, [%4];"
                 : "=r"(r[0]), "=r"(r[1]), "=r"(r[2]), "=r"(r[3]) : "r"(addr));
}
static __device__ __forceinline__ void ldsm4t(uint32_t r[4], uint32_t addr) {
    asm volatile("ldmatrix.sync.aligned.m8n8.x4.trans.shared.b16 {%0,%1,%2,%3}, [%4];"
                 : "=r"(r[0]), "=r"(r[1]), "=r"(r[2]), "=r"(r[3]) : "r"(addr));
}
static __device__ __forceinline__ void mma16816(float d[4],
                                                const uint32_t a[4],
                                                uint32_t b0, uint32_t b1) {
    asm volatile(
        "mma.sync.aligned.m16n8k16.row.col.f32.f16.f16.f32 "
        "{%0,%1,%2,%3}, {%4,%5,%6,%7}, {%8,%9}, {%0,%1,%2,%3};"
        : "+f"(d[0]), "+f"(d[1]), "+f"(d[2]), "+f"(d[3])
        : "r"(a[0]), "r"(a[1]), "r"(a[2]), "r"(a[3]), "r"(b0), "r"(b1));
}
#define CP16(dst, src) \
    asm volatile("cp.async.cg.shared.global [%0], [%1], 16;" :: "r"(dst), "l"(src) : "memory")
#define CPCOMMIT() asm volatile("cp.async.commit_group;" ::: "memory")
#define CPWAIT(n)  asm volatile("cp.async.wait_group %0;" :: "n"(n) : "memory")

// ---------------------------------------------------------------------------
// Pre-kernel: swizzled fp16 image of W^T ([n][k], k contiguous), hi only.
// ---------------------------------------------------------------------------
__global__ void build_w_images(const float* __restrict__ Wq,
                               const float* __restrict__ Wk,
                               const float* __restrict__ Wv)
{
    int gid = blockIdx.x * blockDim.x + threadIdx.x;
    int c   = gid / 3072;
    int u   = gid % 3072;
    int n   = u >> 4;
    int j   = u & 15;
    int k0  = c * 128 + j * 8;

    const float* Wsrc = (n < 64) ? (Wq + n) : (n < 128) ? (Wk + n - 64) : (Wv + n - 128);
    float f[8];
    #pragma unroll
    for (int e = 0; e < 8; ++e) f[e] = Wsrc[(size_t)(k0 + e) * cfg::H];

    uint32_t h[4];
    #pragma unroll
    for (int p = 0; p < 4; ++p) h[p] = pkh(f[2 * p], f[2 * p + 1]);

    size_t off = (size_t)c * 49152 + (size_t)n * 256 + (size_t)((j ^ (n & 7)) << 4);
    *(uint4*)(g_Wh + off) = make_uint4(h[0], h[1], h[2], h[3]);
}

// ---------------------------------------------------------------------------
// Main kernel: 256 threads/CTA, one batch/CTA, 2 CTAs per SM.
// GEMM in 3 N-parts (Q,K,V); attention with in-warp online softmax.
// ---------------------------------------------------------------------------
__global__ __launch_bounds__(256, 2)
void attn_head_kernel(const float* __restrict__ x,
                      float* __restrict__ out)
{
    using namespace cfg;
    extern __shared__ __align__(1024) unsigned char smraw[];
    unsigned char* smc = smraw;

    const int tid = threadIdx.x;
    const int wid = tid >> 5;          // 0..7
    const int lid = tid & 31;
    const int b   = blockIdx.x;
    const uint32_t sb = smem_u32(smraw);
    const float* xb = x + (size_t)b * (T * E);

    // ===== Prefetch W pieces 0 (Q,c0) and 1 (Q,c1) =====
    #pragma unroll
    for (int k = 0; k < 4; ++k) {
        int u = k * 256 + tid;
        CP16(sb + BBUF_B + u * 16, g_Wh + u * 16);
    }
    CPCOMMIT();
    #pragma unroll
    for (int k = 0; k < 4; ++k) {
        int u = k * 256 + tid;
        CP16(sb + BBUF_B + 16384 + u * 16, g_Wh + 49152 + u * 16);
    }
    CPCOMMIT();

    // ===== GEMM warp-tile constants: 4m x 2n grid, tile 32x32 per part =====
    const int mbase = (wid >> 1) * 32;
    const int nbw   = (wid & 1) * 32;
    const int arow  = mbase + (lid & 7) + ((lid >> 3) & 1) * 8;
    const int axor  = arow & 7;
    const int ajsel = (lid >> 4) & 1;
    const int brow  = nbw + (lid & 7) + ((lid >> 4) & 1) * 8;
    const int bxor  = brow & 7;
    const int bjsel = (lid >> 3) & 1;
    const uint32_t abase = sb + A_B + arow * 256;

    float acc[2][4][4];

    // ===== 6 pieces: i = p*2 + c  (p: 0=Q, 1=K, 2=V; c: k-chunk) =====
    #pragma unroll 1
    for (int i = 0; i < 6; ++i) {
        const int p = i >> 1;
        const int c = i & 1;
        if (c == 0) {
            #pragma unroll
            for (int mt = 0; mt < 2; ++mt)
                #pragma unroll
                for (int nt = 0; nt < 4; ++nt)
                    #pragma unroll
                    for (int r = 0; r < 4; ++r) acc[mt][nt][r] = 0.f;
        }

        // convert x chunk c -> A image (overlaps cp.async in flight)
        #pragma unroll
        for (int k = 0; k < 8; ++k) {
            int u = k * 256 + tid;
            int row = u >> 4, j = u & 15;
            const float4* src = (const float4*)(xb + (size_t)row * E + c * 128 + j * 8);
            float4 fa = src[0], fb = src[1];
            uint32_t h0 = pkh(fa.x, fa.y), h1 = pkh(fa.z, fa.w);
            uint32_t h2 = pkh(fb.x, fb.y), h3 = pkh(fb.z, fb.w);
            *(uint4*)(smc + A_B + row * 256 + ((j ^ (row & 7)) << 4)) =
                make_uint4(h0, h1, h2, h3);
        }
        if (i < 5) CPWAIT(1); else CPWAIT(0);
        __syncthreads();    // A + W piece i visible to all warps

        const uint32_t bbase = sb + BBUF_B + (uint32_t)(i & 1) * 16384 + brow * 256;
        #pragma unroll
        for (int s = 0; s < 8; ++s) {
            uint32_t aoff = (uint32_t)(((2 * s + ajsel) ^ axor) << 4);
            uint32_t boff = (uint32_t)(((2 * s + bjsel) ^ bxor) << 4);
            uint32_t ah[2][4];
            ldsm4(ah[0], abase + aoff);
            ldsm4(ah[1], abase + 4096 + aoff);
            #pragma unroll
            for (int g = 0; g < 2; ++g) {
                uint32_t bh[4];
                ldsm4(bh, bbase + g * 4096 + boff);
                #pragma unroll
                for (int mt = 0; mt < 2; ++mt) {
                    mma16816(acc[mt][2 * g + 0], ah[mt], bh[0], bh[1]);
                    mma16816(acc[mt][2 * g + 1], ah[mt], bh[2], bh[3]);
                }
            }
        }

        if (c == 1) {
            // epilogue: part p -> fp16 hi image (Q scaled 1/8)
            const int er = lid >> 2;
            const int c4 = lid & 3;
            const int imgB = (p == 0) ? QHI_B : (p == 1) ? KHI_B : VHI_B;
            const float sc = (p == 0) ? 0.125f : 1.f;
            #pragma unroll
            for (int mt = 0; mt < 2; ++mt)
                #pragma unroll
                for (int nt = 0; nt < 4; ++nt) {
                    int u   = (wid & 1) * 4 + nt;
                    int row = mbase + mt * 16 + er;
                    int rw8 = row + 8;
                    uint32_t h0 = pkh(sc * acc[mt][nt][0], sc * acc[mt][nt][1]);
                    uint32_t h1 = pkh(sc * acc[mt][nt][2], sc * acc[mt][nt][3]);
                    *(uint32_t*)(smc + imgB + row * 128 + ((u ^ (row & 7)) << 4) + c4 * 4) = h0;
                    *(uint32_t*)(smc + imgB + rw8 * 128 + ((u ^ (rw8 & 7)) << 4) + c4 * 4) = h1;
                }
        }
        __syncthreads();    // A dead, piece i consumed, epilogue visible

        if (i + 2 < 6) {
            int i2 = i + 2, p2 = i2 >> 1, c2 = i2 & 1;
            #pragma unroll
            for (int k = 0; k < 4; ++k) {
                int u = k * 256 + tid;
                CP16(sb + BBUF_B + (uint32_t)(i2 & 1) * 16384 + u * 16,
                     g_Wh + (size_t)c2 * 49152 + (size_t)p2 * 16384 + u * 16);
            }
            CPCOMMIT();
        }
    }

    // ===== Attention: one warp per stripe, in-warp online softmax =====
    const int qs = (wid < 4) ? wid : 11 - wid;   // SMSP-balanced stripes
    const int rw = qs * 16;
    const int rofsA = (lid & 7) + ((lid >> 3) & 1) * 8;
    const int jselA = (lid >> 4) & 1;
    const int rofsK = (lid & 7) + ((lid >> 4) & 1) * 8;
    const int jselK = (lid >> 3) & 1;
    const int xorr  = lid & 7;
    const int vub   = (lid >> 4) & 1;
    const int r0    = lid >> 2;
    const int cq    = (lid & 3) * 2;
    const int rowh  = rw + r0;
    const int rowl  = rowh + 8;

    uint32_t qh[4][4];
    #pragma unroll
    for (int s = 0; s < 4; ++s) {
        uint32_t off = (uint32_t)((rw + rofsA) * 128 + (((2 * s + jselA) ^ xorr) << 4));
        ldsm4(qh[s], sb + QHI_B + off);
    }

    float oacc[8][4];
    #pragma unroll
    for (int nb = 0; nb < 8; ++nb)
        #pragma unroll
        for (int r = 0; r < 4; ++r) oacc[nb][r] = 0.f;

    float m0 = -1e30f, m1 = -1e30f, s0 = 0.f, s1 = 0.f;

    #pragma unroll 1
    for (int pb = 0; pb <= qs; ++pb) {
        // S block (16x16), 1-term
        float sa0[4] = {0.f, 0.f, 0.f, 0.f};
        float sa1[4] = {0.f, 0.f, 0.f, 0.f};
        #pragma unroll
        for (int s = 0; s < 4; ++s) {
            uint32_t kh[4];
            uint32_t off = (uint32_t)((16 * pb + rofsK) * 128 +
                                      (((2 * s + jselK) ^ xorr) << 4));
            ldsm4(kh, sb + KHI_B + off);
            mma16816(sa0, qh[s], kh[0], kh[1]);
            mma16816(sa1, qh[s], kh[2], kh[3]);
        }
        if (pb == qs) {   // causal mask on diagonal block
            int colb0 = 16 * pb + cq;
            int colb1 = colb0 + 8;
            if (colb0     > rowh) sa0[0] = -1e30f;
            if (colb0 + 1 > rowh) sa0[1] = -1e30f;
            if (colb0     > rowl) sa0[2] = -1e30f;
            if (colb0 + 1 > rowl) sa0[3] = -1e30f;
            if (colb1     > rowh) sa1[0] = -1e30f;
            if (colb1 + 1 > rowh) sa1[1] = -1e30f;
            if (colb1     > rowl) sa1[2] = -1e30f;
            if (colb1 + 1 > rowl) sa1[3] = -1e30f;
        }
        // online softmax update
        float bm0 = fmaxf(fmaxf(sa0[0], sa0[1]), fmaxf(sa1[0], sa1[1]));
        float bm1 = fmaxf(fmaxf(sa0[2], sa0[3]), fmaxf(sa1[2], sa1[3]));
        bm0 = fmaxf(bm0, __shfl_xor_sync(0xffffffffu, bm0, 1));
        bm0 = fmaxf(bm0, __shfl_xor_sync(0xffffffffu, bm0, 2));
        bm1 = fmaxf(bm1, __shfl_xor_sync(0xffffffffu, bm1, 1));
        bm1 = fmaxf(bm1, __shfl_xor_sync(0xffffffffu, bm1, 2));
        float nm0 = fmaxf(m0, bm0), nm1 = fmaxf(m1, bm1);
        float sc0 = __expf(m0 - nm0), sc1 = __expf(m1 - nm1);
        sa0[0] = __expf(sa0[0] - nm0); sa0[1] = __expf(sa0[1] - nm0);
        sa0[2] = __expf(sa0[2] - nm1); sa0[3] = __expf(sa0[3] - nm1);
        sa1[0] = __expf(sa1[0] - nm0); sa1[1] = __expf(sa1[1] - nm0);
        sa1[2] = __expf(sa1[2] - nm1); sa1[3] = __expf(sa1[3] - nm1);
        float bs0 = sa0[0] + sa0[1] + sa1[0] + sa1[1];
        float bs1 = sa0[2] + sa0[3] + sa1[2] + sa1[3];
        bs0 += __shfl_xor_sync(0xffffffffu, bs0, 1);
        bs0 += __shfl_xor_sync(0xffffffffu, bs0, 2);
        bs1 += __shfl_xor_sync(0xffffffffu, bs1, 1);
        bs1 += __shfl_xor_sync(0xffffffffu, bs1, 2);
        s0 = s0 * sc0 + bs0;
        s1 = s1 * sc1 + bs1;
        #pragma unroll
        for (int nb = 0; nb < 8; ++nb) {
            oacc[nb][0] *= sc0; oacc[nb][1] *= sc0;
            oacc[nb][2] *= sc1; oacc[nb][3] *= sc1;
        }
        m0 = nm0; m1 = nm1;
        // P fragment (fp16, 1-term) and PV accumulate
        uint32_t ph[4];
        ph[0] = pkh(sa0[0], sa0[1]);
        ph[1] = pkh(sa0[2], sa0[3]);
        ph[2] = pkh(sa1[0], sa1[1]);
        ph[3] = pkh(sa1[2], sa1[3]);
        #pragma unroll
        for (int cg = 0; cg < 4; ++cg) {
            uint32_t vh[4];
            uint32_t off = (uint32_t)((16 * pb + rofsA) * 128 +
                                      (((2 * cg + vub) ^ xorr) << 4));
            ldsm4t(vh, sb + VHI_B + off);
            mma16816(oacc[2 * cg + 0], ph, vh[0], vh[1]);
            mma16816(oacc[2 * cg + 1], ph, vh[2], vh[3]);
        }
    }

    const float inv0 = 1.f / s0;
    const float inv1 = 1.f / s1;
    float* ob = out + (size_t)b * T * H;
    #pragma unroll
    for (int nb = 0; nb < 8; ++nb) {
        int col = 8 * nb + cq;
        float2 v0; v0.x = oacc[nb][0] * inv0; v0.y = oacc[nb][1] * inv0;
        float2 v1; v1.x = oacc[nb][2] * inv1; v1.y = oacc[nb][3] * inv1;
        *(float2*)(ob + rowh * H + col) = v0;
        *(float2*)(ob + rowl * H + col) = v1;
    }
}

// ---------------------------------------------------------------------------
extern "C" void kernel_launch(void* const* d_in, const int* in_sizes, int n_in,
                              void* d_out, int out_size)
{
    using namespace cfg;
    const float* x  = (const float*)d_in[0];
    const float* Wq = (const float*)d_in[1];
    const float* Wk = (const float*)d_in[2];
    const float* Wv = (const float*)d_in[3];
    float* out = (float*)d_out;

    const int B = in_sizes[0] / (T * E);

    build_w_images<<<24, 256>>>(Wq, Wk, Wv);

    cudaFuncSetAttribute(attn_head_kernel,
                         cudaFuncAttributeMaxDynamicSharedMemorySize, SMEM_BYTES);
    attn_head_kernel<<<B, 256, SMEM_BYTES>>>(x, out);
}